// round 1
// baseline (speedup 1.0000x reference)
#include <cuda_runtime.h>
#include <cuda_bf16.h>

// ---------------- problem constants ----------------
#define BATCHES   16
#define NC_PER    1024
#define NF_PER    4096
#define NC_TOT    (BATCHES * NC_PER)   // 16384
#define NF_TOT    (BATCHES * NF_PER)   // 65536
#define C_IN      512
#define C_SKIP    256
#define D_IN      (C_IN + C_SKIP)      // 768
#define C_OUT     512
#define BN_EPS    1e-5f

// ---------------- device scratch (static; allocation-free rule) ----------------
__device__ float g_h0[(size_t)NF_TOT * D_IN];    // interpolated + skip concat  [65536,768]
__device__ float g_h1[(size_t)NF_TOT * C_OUT];   // GEMM1 raw output            [65536,512]
__device__ float g_h2[(size_t)NF_TOT * C_OUT];   // GEMM2 raw output            [65536,512]
__device__ int   g_kidx[(size_t)NF_TOT * 3];
__device__ float g_kw[(size_t)NF_TOT * 3];
__device__ float g_psum[256 * C_OUT];            // per-block partial column sums
__device__ float g_psq[256 * C_OUT];
__device__ float g_a1[C_OUT], g_c1[C_OUT], g_a2[C_OUT], g_c2[C_OUT];

// ---------------- f32x2 helpers (Blackwell packed fp32, 2x FFMA throughput) ----------------
__device__ __forceinline__ unsigned long long pack2(float x) {
    unsigned long long r;
    asm("mov.b64 %0, {%1, %1};" : "=l"(r) : "r"(__float_as_uint(x)));
    return r;
}
__device__ __forceinline__ unsigned long long fma2(unsigned long long a,
                                                   unsigned long long b,
                                                   unsigned long long c) {
    unsigned long long d;
    asm("fma.rn.f32x2 %0, %1, %2, %3;" : "=l"(d) : "l"(a), "l"(b), "l"(c));
    return d;
}

// ---------------- kNN (K=3) ----------------
// 256 threads / block, one fine point per thread; 16 blocks per batch.
__global__ __launch_bounds__(256) void knn_kernel(
    const float* __restrict__ pos, const float* __restrict__ pos_skip,
    int* __restrict__ idx_out, float* __restrict__ w_out)
{
    __shared__ float sx[NC_PER], sy[NC_PER], sz[NC_PER], sn[NC_PER];
    int blk = blockIdx.x;
    int b = blk >> 4;                      // 4096/256 = 16 blocks per batch
    const float* pc = pos + (size_t)b * NC_PER * 3;
    for (int i = threadIdx.x; i < NC_PER; i += 256) {
        float px = pc[i*3+0], py = pc[i*3+1], pz = pc[i*3+2];
        sx[i] = px; sy[i] = py; sz[i] = pz;
        sn[i] = px*px + py*py + pz*pz;
    }
    __syncthreads();

    int f = blk * 256 + threadIdx.x;
    float fx = pos_skip[f*3+0], fy = pos_skip[f*3+1], fz = pos_skip[f*3+2];
    float fn = fx*fx + fy*fy + fz*fz;

    float d0 = 3.4e38f, d1 = 3.4e38f, d2 = 3.4e38f;
    int   i0 = 0, i1 = 0, i2 = 0;
    for (int c = 0; c < NC_PER; ++c) {
        float dot = fx*sx[c] + fy*sy[c] + fz*sz[c];
        float dd  = fn + sn[c] - 2.0f*dot;   // same formula as reference
        if (dd < d2) {
            if (dd < d1) {
                if (dd < d0) { d2=d1; i2=i1; d1=d0; i1=i0; d0=dd; i0=c; }
                else         { d2=d1; i2=i1; d1=dd; i1=c; }
            } else           { d2=dd; i2=c; }
        }
    }
    float w0 = 1.0f / fmaxf(d0, 1e-16f);
    float w1 = 1.0f / fmaxf(d1, 1e-16f);
    float w2 = 1.0f / fmaxf(d2, 1e-16f);
    float inv = 1.0f / (w0 + w1 + w2);
    idx_out[f*3+0] = b * NC_PER + i0;
    idx_out[f*3+1] = b * NC_PER + i1;
    idx_out[f*3+2] = b * NC_PER + i2;
    w_out[f*3+0] = w0 * inv;
    w_out[f*3+1] = w1 * inv;
    w_out[f*3+2] = w2 * inv;
}

// ---------------- interpolate + concat -> g_h0 ----------------
// one block (128 threads) per fine point; float4 rows (x is L2-resident: 32MB)
__global__ __launch_bounds__(128) void interp_kernel(
    const float* __restrict__ x, const float* __restrict__ x_skip)
{
    int f = blockIdx.x;
    int t = threadIdx.x;
    int ia = g_kidx[f*3+0], ib = g_kidx[f*3+1], ic = g_kidx[f*3+2];
    float w0 = g_kw[f*3+0], w1 = g_kw[f*3+1], w2 = g_kw[f*3+2];
    const float4* xa = (const float4*)(x + (size_t)ia * C_IN);
    const float4* xb = (const float4*)(x + (size_t)ib * C_IN);
    const float4* xc = (const float4*)(x + (size_t)ic * C_IN);
    float4 a = xa[t], b = xb[t], c = xc[t];
    float4 r;
    r.x = w0*a.x + w1*b.x + w2*c.x;
    r.y = w0*a.y + w1*b.y + w2*c.y;
    r.z = w0*a.z + w1*b.z + w2*c.z;
    r.w = w0*a.w + w1*b.w + w2*c.w;
    float4* out = (float4*)(g_h0 + (size_t)f * D_IN);
    out[t] = r;                                   // 128 float4 = 512 channels
    if (t < C_SKIP / 4)
        out[C_IN/4 + t] = ((const float4*)(x_skip + (size_t)f * C_SKIP))[t];
}

// ---------------- SGEMM 128x128x8, 256 threads, 8x8 microtile, f32x2 accum ----------------
// C[M,N] = A[M,K] @ B[K,N] + bias.  If TRANSA: A is transformed elementwise as
// relu(bna[k]*A + bnc[k]) on load (fused BN1+ReLU feeding GEMM2).
template<bool TRANSA>
__global__ __launch_bounds__(256, 2) void sgemm_kernel(
    const float* __restrict__ A, const float* __restrict__ B,
    const float* __restrict__ bias,
    const float* __restrict__ bna, const float* __restrict__ bnc,
    float* __restrict__ C, int M, int N, int Kd)
{
    __shared__ __align__(16) float As[8 * 128];   // [kk][row]
    __shared__ __align__(16) float Bs[8 * 128];   // [kk][col]
    int tid = threadIdx.x;
    int bx = blockIdx.x;   // column block (N/128)
    int by = blockIdx.y;   // row block    (M/128)

    const float* Ablk = A + (size_t)by * 128 * Kd;
    const float* Bblk = B + (size_t)bx * 128;

    int arow  = tid >> 1;          // 0..127
    int acol4 = (tid & 1) * 4;     // 0 or 4
    int brow  = tid >> 5;          // 0..7
    int bcol4 = (tid & 31) * 4;    // 0..124
    int trow  = (tid >> 4) * 8;
    int tcol  = (tid & 15) * 8;

    unsigned long long acc[8][4];
    #pragma unroll
    for (int i = 0; i < 8; ++i)
        #pragma unroll
        for (int j = 0; j < 4; ++j) acc[i][j] = 0ULL;

    for (int k0 = 0; k0 < Kd; k0 += 8) {
        float4 av = *(const float4*)(Ablk + (size_t)arow * Kd + k0 + acol4);
        if (TRANSA) {
            int kg = k0 + acol4;
            av.x = fmaxf(fmaf(__ldg(bna+kg+0), av.x, __ldg(bnc+kg+0)), 0.0f);
            av.y = fmaxf(fmaf(__ldg(bna+kg+1), av.y, __ldg(bnc+kg+1)), 0.0f);
            av.z = fmaxf(fmaf(__ldg(bna+kg+2), av.z, __ldg(bnc+kg+2)), 0.0f);
            av.w = fmaxf(fmaf(__ldg(bna+kg+3), av.w, __ldg(bnc+kg+3)), 0.0f);
        }
        As[(acol4+0)*128 + arow] = av.x;
        As[(acol4+1)*128 + arow] = av.y;
        As[(acol4+2)*128 + arow] = av.z;
        As[(acol4+3)*128 + arow] = av.w;
        *(float4*)(Bs + brow*128 + bcol4) =
            *(const float4*)(Bblk + (size_t)(k0 + brow) * N + bcol4);
        __syncthreads();

        #pragma unroll
        for (int kk = 0; kk < 8; ++kk) {
            float4 a0 = *(const float4*)(As + kk*128 + trow);
            float4 a1 = *(const float4*)(As + kk*128 + trow + 4);
            unsigned long long ap[8];
            ap[0] = pack2(a0.x); ap[1] = pack2(a0.y);
            ap[2] = pack2(a0.z); ap[3] = pack2(a0.w);
            ap[4] = pack2(a1.x); ap[5] = pack2(a1.y);
            ap[6] = pack2(a1.z); ap[7] = pack2(a1.w);
            const unsigned long long* bp =
                (const unsigned long long*)(Bs + kk*128 + tcol);
            unsigned long long b0 = bp[0], b1 = bp[1], b2 = bp[2], b3 = bp[3];
            #pragma unroll
            for (int i = 0; i < 8; ++i) {
                acc[i][0] = fma2(ap[i], b0, acc[i][0]);
                acc[i][1] = fma2(ap[i], b1, acc[i][1]);
                acc[i][2] = fma2(ap[i], b2, acc[i][2]);
                acc[i][3] = fma2(ap[i], b3, acc[i][3]);
            }
        }
        __syncthreads();
    }

    float bv[8];
    const float* bptr = bias + (size_t)bx * 128 + tcol;
    #pragma unroll
    for (int j = 0; j < 8; ++j) bv[j] = bptr[j];

    #pragma unroll
    for (int i = 0; i < 8; ++i) {
        float o[8];
        #pragma unroll
        for (int j = 0; j < 4; ++j) {
            unsigned long long v = acc[i][j];
            o[2*j+0] = __uint_as_float((unsigned)(v))       + bv[2*j+0];
            o[2*j+1] = __uint_as_float((unsigned)(v >> 32)) + bv[2*j+1];
        }
        float* Crow = C + (size_t)(by*128 + trow + i) * N + bx*128 + tcol;
        *(float4*)(Crow + 0) = make_float4(o[0], o[1], o[2], o[3]);
        *(float4*)(Crow + 4) = make_float4(o[4], o[5], o[6], o[7]);
    }
}

// ---------------- BN stats: deterministic two-stage column reduction ----------------
// stage 1: 256 blocks, each reduces 256 rows -> g_psum/g_psq[block][512]
__global__ __launch_bounds__(256) void stats_kernel(const float* __restrict__ H)
{
    int r0 = blockIdx.x * 256;
    int t = threadIdx.x;
    float s0 = 0, q0 = 0, s1 = 0, q1 = 0;
    for (int r = r0; r < r0 + 256; ++r) {
        float v0 = H[(size_t)r * C_OUT + t];
        float v1 = H[(size_t)r * C_OUT + t + 256];
        s0 += v0; q0 += v0*v0;
        s1 += v1; q1 += v1*v1;
    }
    g_psum[blockIdx.x * C_OUT + t]       = s0;
    g_psq [blockIdx.x * C_OUT + t]       = q0;
    g_psum[blockIdx.x * C_OUT + t + 256] = s1;
    g_psq [blockIdx.x * C_OUT + t + 256] = q1;
}

// stage 2: fold partials -> per-channel affine (a = g*rsqrt(var+eps), c = be - mu*a)
__global__ __launch_bounds__(128) void finalize_kernel(
    const float* __restrict__ g, const float* __restrict__ be,
    float* __restrict__ a, float* __restrict__ c)
{
    int ch = blockIdx.x * 128 + threadIdx.x;
    float s = 0, q = 0;
    for (int p = 0; p < 256; ++p) {
        s += g_psum[p * C_OUT + ch];
        q += g_psq [p * C_OUT + ch];
    }
    float mu  = s * (1.0f / NF_TOT);
    float var = q * (1.0f / NF_TOT) - mu * mu;
    float av  = g[ch] * rsqrtf(var + BN_EPS);
    a[ch] = av;
    c[ch] = be[ch] - mu * av;
}

// ---------------- final BN2 + ReLU -> output h region ----------------
__global__ __launch_bounds__(256) void apply_out_kernel(
    const float* __restrict__ H, float* __restrict__ out)
{
    size_t i = (size_t)blockIdx.x * 256 + threadIdx.x;   // one float4
    int cb = (int)(i & (C_OUT/4 - 1));
    float4 h  = ((const float4*)H)[i];
    float4 av = ((const float4*)g_a2)[cb];
    float4 cv = ((const float4*)g_c2)[cb];
    float4 r;
    r.x = fmaxf(fmaf(av.x, h.x, cv.x), 0.0f);
    r.y = fmaxf(fmaf(av.y, h.y, cv.y), 0.0f);
    r.z = fmaxf(fmaf(av.z, h.z, cv.z), 0.0f);
    r.w = fmaxf(fmaf(av.w, h.w, cv.w), 0.0f);
    ((float4*)out)[i] = r;
}

// ---------------- extra tuple outputs: pos_skip passthrough + batch ids ----------------
__global__ __launch_bounds__(256) void extras_kernel(
    const float* __restrict__ pos_skip, float* __restrict__ out, int mode)
{
    int i = blockIdx.x * 256 + threadIdx.x;
    const size_t baseH = (size_t)NF_TOT * C_OUT;
    if (i < NF_TOT * 3) out[baseH + i] = pos_skip[i];
    if (i < NF_TOT) {
        if (mode == 1)
            out[baseH + NF_TOT*3 + i] = (float)(i >> 12);          // i / NF_PER
        else if (mode == 2)
            ((long long*)(out + baseH + NF_TOT*3))[i] = (long long)(i >> 12);
    }
}

// ---------------- host ----------------
extern "C" void kernel_launch(void* const* d_in, const int* in_sizes, int n_in,
                              void* d_out, int out_size)
{
    const float* x        = (const float*)d_in[0];
    const float* pos      = (const float*)d_in[1];
    const float* x_skip   = (const float*)d_in[3];
    const float* pos_skip = (const float*)d_in[4];
    const float* W1  = (const float*)d_in[6];
    const float* b1  = (const float*)d_in[7];
    const float* g1  = (const float*)d_in[8];
    const float* be1 = (const float*)d_in[9];
    const float* W2  = (const float*)d_in[10];
    const float* b2  = (const float*)d_in[11];
    const float* g2  = (const float*)d_in[12];
    const float* be2 = (const float*)d_in[13];
    float* out = (float*)d_out;

    float *p_h0, *p_h1, *p_h2, *p_a1, *p_c1, *p_a2, *p_c2;
    cudaGetSymbolAddress((void**)&p_h0, g_h0);
    cudaGetSymbolAddress((void**)&p_h1, g_h1);
    cudaGetSymbolAddress((void**)&p_h2, g_h2);
    cudaGetSymbolAddress((void**)&p_a1, g_a1);
    cudaGetSymbolAddress((void**)&p_c1, g_c1);
    cudaGetSymbolAddress((void**)&p_a2, g_a2);
    cudaGetSymbolAddress((void**)&p_c2, g_c2);
    int *p_kidx; float *p_kw;
    cudaGetSymbolAddress((void**)&p_kidx, g_kidx);
    cudaGetSymbolAddress((void**)&p_kw,   g_kw);

    // 1) kNN + weights
    knn_kernel<<<NF_TOT / 256, 256>>>(pos, pos_skip, p_kidx, p_kw);
    // 2) interpolate + concat skip -> h0 [65536,768]
    interp_kernel<<<NF_TOT, 128>>>(x, x_skip);
    // 3) GEMM1: h0 @ W1 + b1 -> h1 (raw)
    {
        dim3 grid(C_OUT / 128, NF_TOT / 128);
        sgemm_kernel<false><<<grid, 256>>>(p_h0, W1, b1, nullptr, nullptr,
                                           p_h1, NF_TOT, C_OUT, D_IN);
    }
    // 4) BN1 stats
    stats_kernel<<<NF_TOT / 256, 256>>>(p_h1);
    finalize_kernel<<<C_OUT / 128, 128>>>(g1, be1, p_a1, p_c1);
    // 5) GEMM2 with fused BN1+ReLU on A: relu(a1*h1+c1) @ W2 + b2 -> h2 (raw)
    {
        dim3 grid(C_OUT / 128, NF_TOT / 128);
        sgemm_kernel<true><<<grid, 256>>>(p_h1, W2, b2, p_a1, p_c1,
                                          p_h2, NF_TOT, C_OUT, C_OUT);
    }
    // 6) BN2 stats
    stats_kernel<<<NF_TOT / 256, 256>>>(p_h2);
    finalize_kernel<<<C_OUT / 128, 128>>>(g2, be2, p_a2, p_c2);
    // 7) BN2 + ReLU -> out h region
    apply_out_kernel<<<(NF_TOT * (C_OUT / 4)) / 256, 256>>>(p_h2, out);
    // 8) tuple extras, sized by out_size
    {
        long long baseH = (long long)NF_TOT * C_OUT;
        long long rem = (long long)out_size - baseH - (long long)NF_TOT * 3;
        int mode = 0;
        if (rem >= 2LL * NF_TOT)      mode = 2;   // raw int64 batch ids
        else if (rem >= (long long)NF_TOT) mode = 1; // batch ids as float
        if ((long long)out_size >= baseH + (long long)NF_TOT * 3)
            extras_kernel<<<(NF_TOT * 3 + 255) / 256, 256>>>(pos_skip, out, mode);
    }
}

// round 3
// speedup vs baseline: 2.4626x; 2.4626x over previous
#include <cuda_runtime.h>
#include <cuda_bf16.h>
#include <cstdint>

// ---------------- problem constants ----------------
#define BATCHES   16
#define NC_PER    1024
#define NF_PER    4096
#define NC_TOT    (BATCHES * NC_PER)   // 16384
#define NF_TOT    (BATCHES * NF_PER)   // 65536
#define C_IN      512
#define C_SKIP    256
#define D_IN      (C_IN + C_SKIP)      // 768
#define C_OUT     512
#define BN_EPS    1e-5f

// ---------------- device scratch ----------------
__device__ __align__(128) __nv_bfloat16 g_h0hi[(size_t)NF_TOT * D_IN];
__device__ __align__(128) __nv_bfloat16 g_h0lo[(size_t)NF_TOT * D_IN];
__device__ __align__(128) float         g_h1[(size_t)NF_TOT * C_OUT];
__device__ __align__(128) float         g_h2[(size_t)NF_TOT * C_OUT];
__device__ __align__(128) __nv_bfloat16 g_h1hi[(size_t)NF_TOT * C_OUT];
__device__ __align__(128) __nv_bfloat16 g_h1lo[(size_t)NF_TOT * C_OUT];
__device__ __align__(128) __nv_bfloat16 g_w1thi[(size_t)C_OUT * D_IN];
__device__ __align__(128) __nv_bfloat16 g_w1tlo[(size_t)C_OUT * D_IN];
__device__ __align__(128) __nv_bfloat16 g_w2thi[(size_t)C_OUT * C_OUT];
__device__ __align__(128) __nv_bfloat16 g_w2tlo[(size_t)C_OUT * C_OUT];
__device__ int   g_kidx[(size_t)NF_TOT * 3];
__device__ float g_kw[(size_t)NF_TOT * 3];
__device__ float g_psum[256 * C_OUT];
__device__ float g_psq[256 * C_OUT];
__device__ float g_a1[C_OUT], g_c1[C_OUT], g_a2[C_OUT], g_c2[C_OUT];

// ---------------- helpers ----------------
__device__ __forceinline__ uint32_t smem_u32(const void* p) {
    uint32_t a;
    asm("{ .reg .u64 t; cvta.to.shared.u64 t, %1; cvt.u32.u64 %0, t; }" : "=r"(a) : "l"(p));
    return a;
}
__device__ __forceinline__ void cp16(uint32_t dst, const void* src) {
    asm volatile("cp.async.cg.shared.global [%0], [%1], 16;" :: "r"(dst), "l"(src));
}
__device__ __forceinline__ void cp_commit() {
    asm volatile("cp.async.commit_group;" ::: "memory");
}
__device__ __forceinline__ void cp_wait1() {
    asm volatile("cp.async.wait_group 1;" ::: "memory");
}
__device__ __forceinline__ void ldsm4(uint32_t& r0, uint32_t& r1, uint32_t& r2, uint32_t& r3, uint32_t addr) {
    asm volatile("ldmatrix.sync.aligned.m8n8.x4.shared.b16 {%0,%1,%2,%3}, [%4];"
                 : "=r"(r0), "=r"(r1), "=r"(r2), "=r"(r3) : "r"(addr));
}
__device__ __forceinline__ void mma16816(float* c, const uint32_t* a, const uint32_t* b) {
    asm volatile("mma.sync.aligned.m16n8k16.row.col.f32.bf16.bf16.f32 "
                 "{%0,%1,%2,%3}, {%4,%5,%6,%7}, {%8,%9}, {%0,%1,%2,%3};"
                 : "+f"(c[0]), "+f"(c[1]), "+f"(c[2]), "+f"(c[3])
                 : "r"(a[0]), "r"(a[1]), "r"(a[2]), "r"(a[3]), "r"(b[0]), "r"(b[1]));
}
__device__ __forceinline__ void split2(float v, __nv_bfloat16& h, __nv_bfloat16& l) {
    h = __float2bfloat16(v);
    l = __float2bfloat16(v - __bfloat162float(h));
}

// ---------------- kNN (K=3) ----------------
__global__ __launch_bounds__(256) void knn_kernel(
    const float* __restrict__ pos, const float* __restrict__ pos_skip,
    int* __restrict__ idx_out, float* __restrict__ w_out)
{
    __shared__ float sx[NC_PER], sy[NC_PER], sz[NC_PER], sn[NC_PER];
    int blk = blockIdx.x;
    int b = blk >> 4;
    const float* pc = pos + (size_t)b * NC_PER * 3;
    for (int i = threadIdx.x; i < NC_PER; i += 256) {
        float px = pc[i*3+0], py = pc[i*3+1], pz = pc[i*3+2];
        sx[i] = px; sy[i] = py; sz[i] = pz;
        sn[i] = px*px + py*py + pz*pz;
    }
    __syncthreads();
    int f = blk * 256 + threadIdx.x;
    float fx = pos_skip[f*3+0], fy = pos_skip[f*3+1], fz = pos_skip[f*3+2];
    float fn = fx*fx + fy*fy + fz*fz;
    float d0 = 3.4e38f, d1 = 3.4e38f, d2 = 3.4e38f;
    int   i0 = 0, i1 = 0, i2 = 0;
    for (int c = 0; c < NC_PER; ++c) {
        float dot = fx*sx[c] + fy*sy[c] + fz*sz[c];
        float dd  = fn + sn[c] - 2.0f*dot;
        if (dd < d2) {
            if (dd < d1) {
                if (dd < d0) { d2=d1; i2=i1; d1=d0; i1=i0; d0=dd; i0=c; }
                else         { d2=d1; i2=i1; d1=dd; i1=c; }
            } else           { d2=dd; i2=c; }
        }
    }
    float w0 = 1.0f / fmaxf(d0, 1e-16f);
    float w1 = 1.0f / fmaxf(d1, 1e-16f);
    float w2 = 1.0f / fmaxf(d2, 1e-16f);
    float inv = 1.0f / (w0 + w1 + w2);
    idx_out[f*3+0] = b * NC_PER + i0;
    idx_out[f*3+1] = b * NC_PER + i1;
    idx_out[f*3+2] = b * NC_PER + i2;
    w_out[f*3+0] = w0 * inv;
    w_out[f*3+1] = w1 * inv;
    w_out[f*3+2] = w2 * inv;
}

// ---------------- interpolate + concat -> bf16 hi/lo h0 ----------------
__global__ __launch_bounds__(128) void interp_kernel(
    const float* __restrict__ x, const float* __restrict__ x_skip)
{
    int f = blockIdx.x;
    int t = threadIdx.x;
    int ia = g_kidx[f*3+0], ib = g_kidx[f*3+1], ic = g_kidx[f*3+2];
    float w0 = g_kw[f*3+0], w1 = g_kw[f*3+1], w2 = g_kw[f*3+2];
    float4 a = ((const float4*)(x + (size_t)ia * C_IN))[t];
    float4 b = ((const float4*)(x + (size_t)ib * C_IN))[t];
    float4 c = ((const float4*)(x + (size_t)ic * C_IN))[t];
    float r[4];
    r[0] = w0*a.x + w1*b.x + w2*c.x;
    r[1] = w0*a.y + w1*b.y + w2*c.y;
    r[2] = w0*a.z + w1*b.z + w2*c.z;
    r[3] = w0*a.w + w1*b.w + w2*c.w;
    __nv_bfloat16 h[4], l[4];
    #pragma unroll
    for (int j = 0; j < 4; ++j) split2(r[j], h[j], l[j]);
    size_t base = (size_t)f * D_IN + t * 4;
    *(uint2*)(g_h0hi + base) = *(uint2*)h;
    *(uint2*)(g_h0lo + base) = *(uint2*)l;
    if (t < C_SKIP / 4) {
        float4 s = ((const float4*)(x_skip + (size_t)f * C_SKIP))[t];
        float sv[4] = {s.x, s.y, s.z, s.w};
        #pragma unroll
        for (int j = 0; j < 4; ++j) split2(sv[j], h[j], l[j]);
        size_t base2 = (size_t)f * D_IN + C_IN + t * 4;
        *(uint2*)(g_h0hi + base2) = *(uint2*)h;
        *(uint2*)(g_h0lo + base2) = *(uint2*)l;
    }
}

// ---------------- W transpose + split: Wt[n][k] = W[k][n] ----------------
__global__ __launch_bounds__(256) void wsplit_kernel(
    const float* __restrict__ W, __nv_bfloat16* __restrict__ hi,
    __nv_bfloat16* __restrict__ lo, int Kd, int N)
{
    int id = blockIdx.x * 256 + threadIdx.x;
    if (id >= N * Kd) return;
    int n = id / Kd, k = id % Kd;
    float v = W[(size_t)k * N + n];
    __nv_bfloat16 h, l;
    split2(v, h, l);
    hi[id] = h; lo[id] = l;
}

// ---------------- h1 -> BN1+ReLU -> bf16 hi/lo split ----------------
__global__ __launch_bounds__(256) void h1split_kernel()
{
    size_t i = (size_t)blockIdx.x * 256 + threadIdx.x;
    int cb = (int)(i & (C_OUT/4 - 1));
    float4 hv = ((const float4*)g_h1)[i];
    float4 av = ((const float4*)g_a1)[cb];
    float4 cv = ((const float4*)g_c1)[cb];
    float v[4];
    v[0] = fmaxf(fmaf(av.x, hv.x, cv.x), 0.0f);
    v[1] = fmaxf(fmaf(av.y, hv.y, cv.y), 0.0f);
    v[2] = fmaxf(fmaf(av.z, hv.z, cv.z), 0.0f);
    v[3] = fmaxf(fmaf(av.w, hv.w, cv.w), 0.0f);
    __nv_bfloat16 h[4], l[4];
    #pragma unroll
    for (int j = 0; j < 4; ++j) split2(v[j], h[j], l[j]);
    *(uint2*)(g_h1hi + i * 4) = *(uint2*)h;
    *(uint2*)(g_h1lo + i * 4) = *(uint2*)l;
}

// ---------------- HMMA split-2 bf16 GEMM ----------------
// C[M,512] = A[M,Kd] @ Wt[512,Kd]^T + bias
// CTA tile 128x128, BK=64, 3-stage cp.async pipeline, 8 warps (warp tile 32x64).
// Split-2: D = Ahi*Bhi + Ahi*Blo + Alo*Bhi   (fp32 accum)
#define BK 64
#define REG_BYTES 16384                  // one 128x64 bf16 tile
#define STAGE_BYTES (4 * REG_BYTES)      // Ahi | Alo | Bhi | Blo
#define STAGES 3
#define GEMM_SMEM (STAGES * STAGE_BYTES) // 196608

__device__ __forceinline__ uint32_t swoff(int row, int c) {
    return (uint32_t)(row * 128 + ((c ^ (row & 7)) << 4));
}

__global__ __launch_bounds__(256, 1) void gemm_kernel(
    const __nv_bfloat16* __restrict__ Ahi, const __nv_bfloat16* __restrict__ Alo,
    const __nv_bfloat16* __restrict__ Bhi, const __nv_bfloat16* __restrict__ Blo,
    const float* __restrict__ bias, float* __restrict__ C, int Kd, int nchunk)
{
    extern __shared__ __align__(128) char smem[];
    uint32_t sbase = smem_u32(smem);
    int tid  = threadIdx.x;
    int wid  = tid >> 5, lane = tid & 31;
    int m0 = blockIdx.y * 128;
    int n0 = blockIdx.x * 128;

    const __nv_bfloat16* srcs[4] = {
        Ahi + (size_t)m0 * Kd, Alo + (size_t)m0 * Kd,
        Bhi + (size_t)n0 * Kd, Blo + (size_t)n0 * Kd };

    // ---- stage issue: 4 regions x 1024 16B-chunks, 16 cp.async per thread ----
    auto issue = [&](int sidx, int k0) {
        uint32_t sb = sbase + (uint32_t)sidx * STAGE_BYTES;
        #pragma unroll
        for (int reg = 0; reg < 4; ++reg) {
            const __nv_bfloat16* src = srcs[reg];
            uint32_t rb = sb + (uint32_t)reg * REG_BYTES;
            #pragma unroll
            for (int it = 0; it < 4; ++it) {
                int chunk = it * 256 + tid;
                int row = chunk >> 3, c = chunk & 7;
                cp16(rb + swoff(row, c), src + (size_t)row * Kd + k0 + c * 8);
            }
        }
    };

    issue(0, 0);        cp_commit();
    issue(1, BK);       cp_commit();

    // warp tiling: 4 (M) x 2 (N) warps; warp tile 32(M) x 64(N)
    int wm = wid & 3, wn = wid >> 2;
    int mbase = wm * 32, nbase = wn * 64;
    int sub = lane >> 3, l7 = lane & 7;

    float acc[2][8][4];
    #pragma unroll
    for (int i = 0; i < 2; ++i)
        #pragma unroll
        for (int j = 0; j < 8; ++j)
            #pragma unroll
            for (int q = 0; q < 4; ++q) acc[i][j][q] = 0.0f;

    int arow_l = mbase + ((sub & 1) << 3) + l7;   // A ldmatrix row (within tile)
    int acol_s = (sub >> 1);                       // A chunk sub-offset (0/1)
    int brow_l = nbase + ((sub >> 1) << 3) + l7;   // B ldmatrix n-row
    int bcol_s = (sub & 1);                        // B chunk sub-offset

    for (int cc = 0; cc < nchunk; ++cc) {
        cp_wait1();
        __syncthreads();
        if (cc + 2 < nchunk) issue((cc + 2) % STAGES, (cc + 2) * BK);
        cp_commit();

        uint32_t bb = sbase + (uint32_t)(cc % STAGES) * STAGE_BYTES;
        #pragma unroll
        for (int ks = 0; ks < 4; ++ks) {
            uint32_t ah[2][4], al[2][4], bh[8][2], bl[8][2];
            int achunk = ks * 2 + acol_s;
            #pragma unroll
            for (int mi = 0; mi < 2; ++mi) {
                uint32_t ao = swoff(arow_l + mi * 16, achunk);
                ldsm4(ah[mi][0], ah[mi][1], ah[mi][2], ah[mi][3], bb + ao);
                ldsm4(al[mi][0], al[mi][1], al[mi][2], al[mi][3], bb + REG_BYTES + ao);
            }
            int bchunk = ks * 2 + bcol_s;
            #pragma unroll
            for (int pi = 0; pi < 4; ++pi) {
                uint32_t bo = swoff(brow_l + pi * 16, bchunk);
                ldsm4(bh[pi*2][0], bh[pi*2][1], bh[pi*2+1][0], bh[pi*2+1][1],
                      bb + 2 * REG_BYTES + bo);
                ldsm4(bl[pi*2][0], bl[pi*2][1], bl[pi*2+1][0], bl[pi*2+1][1],
                      bb + 3 * REG_BYTES + bo);
            }
            #pragma unroll
            for (int mi = 0; mi < 2; ++mi)
                #pragma unroll
                for (int ni = 0; ni < 8; ++ni)
                    mma16816(acc[mi][ni], ah[mi], bh[ni]);
            #pragma unroll
            for (int mi = 0; mi < 2; ++mi)
                #pragma unroll
                for (int ni = 0; ni < 8; ++ni)
                    mma16816(acc[mi][ni], ah[mi], bl[ni]);
            #pragma unroll
            for (int mi = 0; mi < 2; ++mi)
                #pragma unroll
                for (int ni = 0; ni < 8; ++ni)
                    mma16816(acc[mi][ni], al[mi], bh[ni]);
        }
    }

    // ---- epilogue: bias add + fp32 store ----
    int grow = m0 + mbase + (lane >> 2);
    int gcol0 = n0 + nbase + (lane & 3) * 2;
    #pragma unroll
    for (int ni = 0; ni < 8; ++ni) {
        int col = gcol0 + ni * 8;
        float bx = __ldg(bias + col), by = __ldg(bias + col + 1);
        #pragma unroll
        for (int mi = 0; mi < 2; ++mi) {
            int r = grow + mi * 16;
            float2 v0 = make_float2(acc[mi][ni][0] + bx, acc[mi][ni][1] + by);
            float2 v1 = make_float2(acc[mi][ni][2] + bx, acc[mi][ni][3] + by);
            *(float2*)(C + (size_t)r * C_OUT + col)       = v0;
            *(float2*)(C + (size_t)(r + 8) * C_OUT + col) = v1;
        }
    }
}

// ---------------- BN stats (two-stage, deterministic) ----------------
__global__ __launch_bounds__(256) void stats_kernel(const float* __restrict__ H)
{
    int r0 = blockIdx.x * 256;
    int t = threadIdx.x;
    float s0 = 0, q0 = 0, s1 = 0, q1 = 0;
    for (int r = r0; r < r0 + 256; ++r) {
        float v0 = H[(size_t)r * C_OUT + t];
        float v1 = H[(size_t)r * C_OUT + t + 256];
        s0 += v0; q0 += v0*v0;
        s1 += v1; q1 += v1*v1;
    }
    g_psum[blockIdx.x * C_OUT + t]       = s0;
    g_psq [blockIdx.x * C_OUT + t]       = q0;
    g_psum[blockIdx.x * C_OUT + t + 256] = s1;
    g_psq [blockIdx.x * C_OUT + t + 256] = q1;
}

__global__ __launch_bounds__(128) void finalize_kernel(
    const float* __restrict__ g, const float* __restrict__ be,
    float* __restrict__ a, float* __restrict__ c)
{
    int ch = blockIdx.x * 128 + threadIdx.x;
    float s = 0, q = 0;
    for (int p = 0; p < 256; ++p) {
        s += g_psum[p * C_OUT + ch];
        q += g_psq [p * C_OUT + ch];
    }
    float mu  = s * (1.0f / NF_TOT);
    float var = q * (1.0f / NF_TOT) - mu * mu;
    float av  = g[ch] * rsqrtf(var + BN_EPS);
    a[ch] = av;
    c[ch] = be[ch] - mu * av;
}

// ---------------- final BN2 + ReLU -> out ----------------
__global__ __launch_bounds__(256) void apply_out_kernel(
    const float* __restrict__ H, float* __restrict__ out)
{
    size_t i = (size_t)blockIdx.x * 256 + threadIdx.x;
    int cb = (int)(i & (C_OUT/4 - 1));
    float4 h  = ((const float4*)H)[i];
    float4 av = ((const float4*)g_a2)[cb];
    float4 cv = ((const float4*)g_c2)[cb];
    float4 r;
    r.x = fmaxf(fmaf(av.x, h.x, cv.x), 0.0f);
    r.y = fmaxf(fmaf(av.y, h.y, cv.y), 0.0f);
    r.z = fmaxf(fmaf(av.z, h.z, cv.z), 0.0f);
    r.w = fmaxf(fmaf(av.w, h.w, cv.w), 0.0f);
    ((float4*)out)[i] = r;
}

// ---------------- tuple extras ----------------
__global__ __launch_bounds__(256) void extras_kernel(
    const float* __restrict__ pos_skip, float* __restrict__ out, int mode)
{
    int i = blockIdx.x * 256 + threadIdx.x;
    const size_t baseH = (size_t)NF_TOT * C_OUT;
    if (i < NF_TOT * 3) out[baseH + i] = pos_skip[i];
    if (i < NF_TOT) {
        if (mode == 1)
            out[baseH + NF_TOT*3 + i] = (float)(i >> 12);
        else if (mode == 2)
            ((long long*)(out + baseH + NF_TOT*3))[i] = (long long)(i >> 12);
    }
}

// ---------------- host ----------------
extern "C" void kernel_launch(void* const* d_in, const int* in_sizes, int n_in,
                              void* d_out, int out_size)
{
    const float* x        = (const float*)d_in[0];
    const float* pos      = (const float*)d_in[1];
    const float* x_skip   = (const float*)d_in[3];
    const float* pos_skip = (const float*)d_in[4];
    const float* W1  = (const float*)d_in[6];
    const float* b1  = (const float*)d_in[7];
    const float* g1  = (const float*)d_in[8];
    const float* be1 = (const float*)d_in[9];
    const float* W2  = (const float*)d_in[10];
    const float* b2  = (const float*)d_in[11];
    const float* g2  = (const float*)d_in[12];
    const float* be2 = (const float*)d_in[13];
    float* out = (float*)d_out;

    float *p_h1, *p_h2, *p_a1, *p_c1, *p_a2, *p_c2;
    cudaGetSymbolAddress((void**)&p_h1, g_h1);
    cudaGetSymbolAddress((void**)&p_h2, g_h2);
    cudaGetSymbolAddress((void**)&p_a1, g_a1);
    cudaGetSymbolAddress((void**)&p_c1, g_c1);
    cudaGetSymbolAddress((void**)&p_a2, g_a2);
    cudaGetSymbolAddress((void**)&p_c2, g_c2);
    int *p_kidx; float *p_kw;
    cudaGetSymbolAddress((void**)&p_kidx, g_kidx);
    cudaGetSymbolAddress((void**)&p_kw,   g_kw);
    __nv_bfloat16 *p_h0hi, *p_h0lo, *p_h1hi, *p_h1lo, *p_w1thi, *p_w1tlo, *p_w2thi, *p_w2tlo;
    cudaGetSymbolAddress((void**)&p_h0hi, g_h0hi);
    cudaGetSymbolAddress((void**)&p_h0lo, g_h0lo);
    cudaGetSymbolAddress((void**)&p_h1hi, g_h1hi);
    cudaGetSymbolAddress((void**)&p_h1lo, g_h1lo);
    cudaGetSymbolAddress((void**)&p_w1thi, g_w1thi);
    cudaGetSymbolAddress((void**)&p_w1tlo, g_w1tlo);
    cudaGetSymbolAddress((void**)&p_w2thi, g_w2thi);
    cudaGetSymbolAddress((void**)&p_w2tlo, g_w2tlo);

    cudaFuncSetAttribute(gemm_kernel, cudaFuncAttributeMaxDynamicSharedMemorySize, GEMM_SMEM);

    // weight prep
    wsplit_kernel<<<(C_OUT * D_IN + 255) / 256, 256>>>(W1, p_w1thi, p_w1tlo, D_IN, C_OUT);
    wsplit_kernel<<<(C_OUT * C_OUT + 255) / 256, 256>>>(W2, p_w2thi, p_w2tlo, C_OUT, C_OUT);
    // 1) kNN
    knn_kernel<<<NF_TOT / 256, 256>>>(pos, pos_skip, p_kidx, p_kw);
    // 2) interpolate + concat -> h0 hi/lo
    interp_kernel<<<NF_TOT, 128>>>(x, x_skip);
    // 3) GEMM1 -> h1 (raw fp32)
    {
        dim3 grid(C_OUT / 128, NF_TOT / 128);
        gemm_kernel<<<grid, 256, GEMM_SMEM>>>(p_h0hi, p_h0lo, p_w1thi, p_w1tlo,
                                              b1, p_h1, D_IN, D_IN / BK);
    }
    // 4) BN1 stats
    stats_kernel<<<NF_TOT / 256, 256>>>(p_h1);
    finalize_kernel<<<C_OUT / 128, 128>>>(g1, be1, p_a1, p_c1);
    // 5) BN1+ReLU+split -> h1 hi/lo
    h1split_kernel<<<(NF_TOT * (C_OUT / 4)) / 256, 256>>>();
    // 6) GEMM2 -> h2 (raw fp32)
    {
        dim3 grid(C_OUT / 128, NF_TOT / 128);
        gemm_kernel<<<grid, 256, GEMM_SMEM>>>(p_h1hi, p_h1lo, p_w2thi, p_w2tlo,
                                              b2, p_h2, C_OUT, C_OUT / BK);
    }
    // 7) BN2 stats
    stats_kernel<<<NF_TOT / 256, 256>>>(p_h2);
    finalize_kernel<<<C_OUT / 128, 128>>>(g2, be2, p_a2, p_c2);
    // 8) BN2 + ReLU -> out
    apply_out_kernel<<<(NF_TOT * (C_OUT / 4)) / 256, 256>>>(p_h2, out);
    // 9) tuple extras
    {
        long long baseH = (long long)NF_TOT * C_OUT;
        long long rem = (long long)out_size - baseH - (long long)NF_TOT * 3;
        int mode = 0;
        if (rem >= 2LL * NF_TOT)      mode = 2;
        else if (rem >= (long long)NF_TOT) mode = 1;
        if ((long long)out_size >= baseH + (long long)NF_TOT * 3)
            extras_kernel<<<(NF_TOT * 3 + 255) / 256, 256>>>(pos_skip, out, mode);
    }
}